// round 15
// baseline (speedup 1.0000x reference)
#include <cuda_runtime.h>
#include <math.h>

#define NN 17
#define DD 512
#define HH 8
#define MM 256
#define CIN 515
#define NB 256          // grid; co-resident (2/SM * 148 = 296 >= 256)

typedef unsigned long long u64;

// ---------------- f32x2 helpers ----------------
__device__ __forceinline__ void ffma2(u64& acc, u64 a, u64 b) {
    asm("fma.rn.f32x2 %0, %1, %2, %0;" : "+l"(acc) : "l"(a), "l"(b));
}
__device__ __forceinline__ u64 dup2(float x) {
    u64 r; asm("mov.b64 %0, {%1, %1};" : "=l"(r) : "f"(x)); return r;
}
__device__ __forceinline__ float2 unpack2(u64 a) {
    float2 f; asm("mov.b64 {%0, %1}, %2;" : "=f"(f.x), "=f"(f.y) : "l"(a)); return f;
}

// ---------------- device scratch ----------------
__device__ float g_pA[16][HH][NN][DD];   // Xs@FC partials, 16 d-chunks (32 wide)
__device__ float g_f[HH][NN][DD];        // f = relu(Xs@FC)
__device__ float g_pB[32][HH][NN][MM];   // cat@W1 partials, 32 c-chunks (16 wide)
__device__ float g_patt[HH][8][NN * NN]; // partial logits per m-chunk [h][mc][n*17+k]

// ---------------- contention-free flag barrier ----------------
// Each block owns one flag in its own 128B line; arrival = release-store of a
// monotonically increasing epoch. Every thread polls ONE distinct flag (tid <->
// block), so the barrier has NO atomic serialization. Replay-safe: epochs only
// grow; per-call base = own flag value at kernel entry (3 barriers per call).
__device__ volatile unsigned g_flag[NB * 32];

__device__ __forceinline__ void gbar_flag(unsigned target) {
    __threadfence();                 // make this block's phase writes visible
    __syncthreads();                 // all threads done + fenced
    if (threadIdx.x == 0)
        g_flag[blockIdx.x * 32] = target;
    while (g_flag[threadIdx.x * 32] < target) __nanosleep(32);
    __threadfence();                 // acquire other blocks' writes
    __syncthreads();
}

// ================= The one persistent kernel =================
// smem union: A 5120 | B 3040 | C1 2560+2176 | C3 1088+1024+576
#define SM_BYTES 12800
__global__ void __launch_bounds__(256, 2)
mega(const float* __restrict__ Xs, const float* __restrict__ ROIs,
     const float* __restrict__ FC, const float* __restrict__ W1,
     const float* __restrict__ b1, const float* __restrict__ W2,
     const float* __restrict__ b2, const float* __restrict__ conv_w,
     const float* __restrict__ conv_b, float* __restrict__ out, int out_size) {
    __shared__ __align__(16) char smbuf[SM_BYTES];
    const int bid = blockIdx.x, tid = threadIdx.x;

    // per-call epoch base: own flag value (identical across blocks at entry)
    const unsigned base = g_flag[bid * 32];

    // ======== Phase A: partial f = Xs @ FC ========
    // bid = dc(16) | ec(1bit) | h(3bit); 32-wide d-chunks; group g over n.
    {
        const int dc = bid & 15, ec = (bid >> 4) & 1, h = bid >> 5;
        const int d0 = dc * 32;
        const int g = tid >> 7;
        const int P = ec * 128 + (tid & 127);   // e-pair

        u64* xsd = reinterpret_cast<u64*>(smbuf);   // [(g*32+dd)*10 + j]
        for (int idx = tid; idx < 32 * 20; idx += 256) {
            int dd = idx / 20, s = idx % 20;
            int gg = s / 10, j = s % 10;
            int n = gg ? 9 + j : j;
            bool ok = gg ? (j < 8) : (j < 9);
            float v = ok ? Xs[n * DD + d0 + dd] : 0.f;
            xsd[(gg * 32 + dd) * 10 + j] = dup2(v);
        }
        __syncthreads();

        u64 acc[10];
#pragma unroll
        for (int j = 0; j < 10; ++j) acc[j] = 0ull;

        const u64* fc = reinterpret_cast<const u64*>(FC)
                      + (size_t)h * 131072 + (size_t)d0 * 256 + P;
        u64 buf[8];
#pragma unroll
        for (int p = 0; p < 8; ++p) buf[p] = fc[(size_t)p * 256];

#pragma unroll
        for (int dd = 0; dd < 32; ++dd) {
            u64 w = buf[dd & 7];
            if (dd < 24) buf[dd & 7] = fc[(size_t)(dd + 8) * 256];
            const ulonglong2* row = reinterpret_cast<const ulonglong2*>(&xsd[(g * 32 + dd) * 10]);
#pragma unroll
            for (int j = 0; j < 5; ++j) {
                ulonglong2 q = row[j];
                ffma2(acc[2 * j],     q.x, w);
                ffma2(acc[2 * j + 1], q.y, w);
            }
        }
        if (g == 0) {
#pragma unroll
            for (int j = 0; j < 9; ++j)
                *reinterpret_cast<u64*>(&g_pA[dc][h][j][2 * P]) = acc[j];
        } else {
#pragma unroll
            for (int j = 0; j < 8; ++j)
                *reinterpret_cast<u64*>(&g_pA[dc][h][9 + j][2 * P]) = acc[j];
        }
    }

    // ---- prefetch phase B's W1 stream (input-only; hides DRAM latency in barrier) ----
    const int Bcc = bid & 31, Bh = bid >> 5;
    const int Bmp = tid & 127;
    const u64* w1p = reinterpret_cast<const u64*>(W1)
                   + (size_t)Bh * 65920 + (size_t)(Bcc * 16) * 128 + Bmp;
    u64 w1buf[8];
#pragma unroll
    for (int p = 0; p < 8; ++p) w1buf[p] = w1p[(size_t)p * 128];

    gbar_flag(base + 1);

    // ======== Phase B: reduce f chunk + relu, partial cat @ W1 ========
    {
        const int cc = Bcc, h = Bh;
        const int c0 = cc * 16;
        const int g = tid >> 7;
        const int mp = Bmp;   // m-pair

        u64* catd = reinterpret_cast<u64*>(smbuf);   // [(g*19+row)*10 + slot]
        for (int idx = tid; idx < 2 * 19 * 10; idx += 256) catd[idx] = 0ull;
        __syncthreads();

        for (int idx = tid; idx < NN * 16; idx += 256) {
            int n = idx >> 4, cp = idx & 15;
            float v = 0.f;
#pragma unroll
            for (int s = 0; s < 16; ++s) v += g_pA[s][h][n][c0 + cp];
            v = fmaxf(v, 0.f);
            g_f[h][n][c0 + cp] = v;
            if (n < 9) catd[(0 * 19 + cp) * 10 + n] = dup2(v);
            else       catd[(1 * 19 + cp) * 10 + (n - 9)] = dup2(v);
        }
        if (cc == 31 && tid < NN * 3) {
            int n = tid / 3, jj = tid % 3;
            float v = ROIs[tid];
            if (n < 9) catd[(0 * 19 + 16 + jj) * 10 + n] = dup2(v);
            else       catd[(1 * 19 + 16 + jj) * 10 + (n - 9)] = dup2(v);
        }
        __syncthreads();

        u64 acc[10];
#pragma unroll
        for (int j = 0; j < 10; ++j) acc[j] = 0ull;

#pragma unroll
        for (int i = 0; i < 16; ++i) {
            u64 w = w1buf[i & 7];
            if (i < 8) w1buf[i & 7] = w1p[(size_t)(i + 8) * 128];
            const ulonglong2* row = reinterpret_cast<const ulonglong2*>(&catd[(g * 19 + i) * 10]);
#pragma unroll
            for (int j = 0; j < 5; ++j) {
                ulonglong2 q = row[j];
                ffma2(acc[2 * j],     q.x, w);
                ffma2(acc[2 * j + 1], q.y, w);
            }
        }
        if (cc == 31) {
#pragma unroll
            for (int jj = 0; jj < 3; ++jj) {
                u64 w = reinterpret_cast<const u64*>(W1)[(size_t)h * 65920 + (size_t)(DD + jj) * 128 + mp];
                const ulonglong2* row = reinterpret_cast<const ulonglong2*>(&catd[(g * 19 + 16 + jj) * 10]);
#pragma unroll
                for (int j = 0; j < 5; ++j) {
                    ulonglong2 q = row[j];
                    ffma2(acc[2 * j],     q.x, w);
                    ffma2(acc[2 * j + 1], q.y, w);
                }
            }
        }
        if (g == 0) {
#pragma unroll
            for (int j = 0; j < 9; ++j)
                *reinterpret_cast<u64*>(&g_pB[cc][h][j][2 * mp]) = acc[j];
        } else {
#pragma unroll
            for (int j = 0; j < 8; ++j)
                *reinterpret_cast<u64*>(&g_pB[cc][h][9 + j][2 * mp]) = acc[j];
        }
    }

    // ---- prefetch phase C1's W2 slab + b1 (inputs) ----
    const int C1mc = bid & 7, C1h = bid >> 3;
    float4 w2pf = make_float4(0.f, 0.f, 0.f, 0.f);
    float4 b1pf = make_float4(0.f, 0.f, 0.f, 0.f);
    if (bid < 64) {
        if (tid < 136)
            w2pf = reinterpret_cast<const float4*>(W2 + ((size_t)C1h * MM + C1mc * 32) * NN)[tid];
        if (tid < NN * 8)
            b1pf = *reinterpret_cast<const float4*>(b1 + C1h * MM + C1mc * 32 + (tid & 7) * 4);
    }

    gbar_flag(base + 2);

    // ======== Phase C1: reduce g_pB + bias + tanh + partial logits ========
    if (bid < 64) {
        const int mc = C1mc, h = C1h;
        const int m0 = mc * 32;
        float* hdnf = reinterpret_cast<float*>(smbuf);            // [lm*20 + n]
        float* W2s  = reinterpret_cast<float*>(smbuf + 2560);     // [lm*17 + k]

        if (tid < NN * 8) {
            int n = tid >> 3, q = tid & 7;
            int m4 = m0 + q * 4;
            float4 s = b1pf;
#pragma unroll
            for (int cc = 0; cc < 32; ++cc) {
                float4 v = *reinterpret_cast<const float4*>(&g_pB[cc][h][n][m4]);
                s.x += v.x; s.y += v.y; s.z += v.z; s.w += v.w;
            }
            int lm = q * 4;
            hdnf[(lm + 0) * 20 + n] = tanhf(s.x);
            hdnf[(lm + 1) * 20 + n] = tanhf(s.y);
            hdnf[(lm + 2) * 20 + n] = tanhf(s.z);
            hdnf[(lm + 3) * 20 + n] = tanhf(s.w);
        }
        if (tid < 136)
            reinterpret_cast<float4*>(W2s)[tid] = w2pf;
        __syncthreads();

        for (int idx = tid; idx < NN * NN; idx += 256) {
            int n = idx / NN, k = idx % NN;
            float s = 0.f;
#pragma unroll
            for (int lm = 0; lm < 32; ++lm)
                s = fmaf(hdnf[lm * 20 + n], W2s[lm * NN + k], s);
            g_patt[h][mc][idx] = s;
        }
    }

    // ---- prefetch phase C3's input-only operands ----
    const int C3k = bid >> 1, C3ec = bid & 1;
    const int C3hg = tid >> 7, C3dt = tid & 127;
    const int C3P = C3ec * 128 + C3dt;
    float b2pf = 0.f, cbpf = 0.f;
    float2 xvpf = make_float2(0.f, 0.f);
    if (bid < 2 * NN) {
        if (tid < HH * NN) b2pf = b2[(tid / NN) * NN + C3k];
        cbpf = conv_b[0];
        if (C3hg == 0)
            xvpf = *reinterpret_cast<const float2*>(Xs + C3k * DD + 2 * C3P);
    }

    gbar_flag(base + 3);

    // ======== Phase C3: per-k softmax + out = relu(sum_{h,n} attw*f + cb) + Xs ========
    if (bid < 2 * NN) {
        const int k = C3k;
        const int hg = C3hg, dt = C3dt;
        const int P = C3P;

        u64*    aw   = reinterpret_cast<u64*>(smbuf);                    // [h*17+n]
        float2* part = reinterpret_cast<float2*>(smbuf + 1088);          // [128]
        float*  law  = reinterpret_cast<float*>(smbuf + 1088 + 1024);    // [h*18+n]

        // 1) reduce logit partials for this k
        if (tid < HH * NN) {
            int h = tid / NN, n = tid % NN;
            float s = b2pf;
#pragma unroll
            for (int q = 0; q < 8; ++q) s += g_patt[h][q][n * NN + k];
            law[h * 18 + n] = s;
        }
        __syncthreads();

        // 2) per-head softmax over n, premultiply conv_w
        if (tid < HH) {
            const int h = tid;
            float mx = -1e30f;
#pragma unroll
            for (int n = 0; n < NN; ++n) mx = fmaxf(mx, law[h * 18 + n]);
            float ex[NN], sum = 0.f;
#pragma unroll
            for (int n = 0; n < NN; ++n) { ex[n] = expf(law[h * 18 + n] - mx); sum += ex[n]; }
            float scale = conv_w[h] / sum;
#pragma unroll
            for (int n = 0; n < NN; ++n) aw[h * NN + n] = dup2(ex[n] * scale);
        }
        __syncthreads();

        // 3) weighted sum over (h, n) of f + conv bias + relu + residual
        const u64* fb = reinterpret_cast<const u64*>(g_f) + P;
        const int hb = hg * 4;

        u64 acc[4];
#pragma unroll
        for (int j = 0; j < 4; ++j) acc[j] = 0ull;

#pragma unroll
        for (int hh = 0; hh < 4; ++hh) {
            const int h = hb + hh;
#pragma unroll
            for (int n = 0; n < NN; ++n) {
                u64 f2 = fb[(size_t)(h * NN + n) * 256];
                ffma2(acc[(hh * NN + n) & 3], aw[h * NN + n], f2);
            }
        }
        float2 a0 = unpack2(acc[0]), a1 = unpack2(acc[1]);
        float2 a2 = unpack2(acc[2]), a3 = unpack2(acc[3]);
        float2 s = make_float2(a0.x + a1.x + a2.x + a3.x,
                               a0.y + a1.y + a2.y + a3.y);
        if (hg == 1) part[dt] = s;
        __syncthreads();
        if (hg == 0) {
            float rx = s.x + part[dt].x + cbpf;
            float ry = s.y + part[dt].y + cbpf;
            float2 r = make_float2(fmaxf(rx, 0.f) + xvpf.x, fmaxf(ry, 0.f) + xvpf.y);
            *reinterpret_cast<float2*>(out + k * DD + 2 * P) = r;
        }
        if (k == 0 && C3ec == 0 && tid < NN * 3 && out_size >= NN * DD + NN * 3)
            out[NN * DD + tid] = ROIs[tid];
    }
}

// ---------------- launch ----------------
extern "C" void kernel_launch(void* const* d_in, const int* in_sizes, int n_in,
                              void* d_out, int out_size) {
    const float *Xs = 0, *ROIs = 0, *FC = 0, *W1 = 0, *b1 = 0, *W2 = 0, *b2 = 0,
                *cw = 0, *cb = 0;
    for (int i = 0; i < n_in; ++i) {
        const float* p = (const float*)d_in[i];
        switch (in_sizes[i]) {
            case NN * DD:       Xs = p; break;
            case NN * 3:        ROIs = p; break;
            case NN * NN:       /* adj */ break;
            case HH * DD * DD:  FC = p; break;
            case HH * CIN * MM: W1 = p; break;
            case HH * MM:       b1 = p; break;
            case HH * MM * NN:  W2 = p; break;
            case HH * NN:       b2 = p; break;
            case HH:            cw = p; break;
            case 1:             cb = p; break;
            default: break;
        }
    }
    float* out = (float*)d_out;

    mega<<<NB, 256>>>(Xs, ROIs, FC, W1, b1, W2, b2, cw, cb, out, out_size);
}